// round 11
// baseline (speedup 1.0000x reference)
#include <cuda_runtime.h>
#include <math.h>

#define N_ROWS   250000
#define N_COLS   100
#define N_BINS   15
#define THREADS  256
#define WARPS    8
#define W_ROWS   4                       // rows per warp-tile
#define N_TILES  (N_ROWS / W_ROWS)       // 62500
#define ROW_PAD  104                     // padded row stride -> conflict-free LDS.128
#define BUF_FLT  (W_ROWS * ROW_PAD)      // 416 floats per buffer
#define N_STAGE  3                       // pipeline depth (prefetch distance 2)
#define GRID     740                     // 148 SMs x 5 resident blocks (smem/regs)
#define NWARP    (GRID * WARPS)          // 5920 warps

// Global accumulators. Zero at module load; the last block re-zeros them
// after finalizing so every graph replay starts clean.
__device__ double   g_sumsq;
__device__ int      g_cc[2 * N_BINS];
__device__ int      g_cf[2 * N_BINS];
__device__ float    g_sf[2 * N_BINS];
__device__ unsigned g_done;

#define CP16I(dst, src, imm) \
    asm volatile("cp.async.cg.shared.global [%0], [%1+" #imm "], 16;" \
                 :: "r"(dst), "l"(src))
#define CP_COMMIT() asm volatile("cp.async.commit_group;" ::: "memory")
#define CP_WAIT(n)  asm volatile("cp.async.wait_group %0;" :: "n"(n) : "memory")

__device__ __forceinline__ float ex2f(float x) {
    float r; asm("ex2.approx.f32 %0, %1;" : "=f"(r) : "f"(x)); return r;
}
#define L2E 1.4426950408889634f

// Bit-exact model of n sequential fp32 RNE additions of the constant a
// (XLA scatter-add of identical addends is order-independent). All-integer:
// per-add increment is RNE(A * 2^(ea-e)) ulps; in-binade advance is u32
// mantissa arithmetic; one genuine fp32 add per binade crossing.
__device__ float seqsum_const_f32(float a, unsigned n) {
    unsigned ai = __float_as_uint(a);
    unsigned A  = (ai & 0x7FFFFFu) | 0x800000u;
    int      ea = (int)((ai >> 23) & 0xFF);
    float s = 0.0f;
    while (n > 0) {
        float s1 = s + a;
        if (s1 == s) break;
        s = s1; n--;
        if (n == 0) break;
        unsigned si   = __float_as_uint(s);
        int      e    = (int)((si >> 23) & 0xFF);
        unsigned mant = (si & 0x7FFFFFu) | 0x800000u;
        int sh = e - ea;
        unsigned step;
        if (sh <= 0)       step = A;
        else if (sh >= 25) step = 0;
        else {
            unsigned q = A >> sh, r = A & ((1u << sh) - 1u), half = 1u << (sh - 1);
            step = q + ((r > half || (r == half && (q & 1u))) ? 1u : 0u);
        }
        if (step != 0) {
            unsigned room = (0xFFFFFFu - mant) / step;
            unsigned m = room < n ? room : n;
            if (m > 0) {
                mant += m * step;
                s = __uint_as_float(((unsigned)e << 23) | (mant & 0x7FFFFFu));
                n -= m;
            }
        }
    }
    return s;
}

__global__ __launch_bounds__(THREADS, 5) void KLECE_main(const float* __restrict__ inp,
                                                         float* __restrict__ out) {
    extern __shared__ float buf[];   // [WARPS][N_STAGE][BUF_FLT]
    __shared__ int    s_hi[WARPS][2];
    __shared__ float  s_hf[WARPS][2];
    __shared__ double s_warp[WARPS];
    __shared__ bool   s_last;

    const int tid = threadIdx.x, lane = tid & 31, wid = tid >> 5;
    const int gwarp = blockIdx.x * WARPS + wid;

    float* wbuf = buf + wid * (N_STAGE * BUF_FLT);
    const unsigned wbase = (unsigned)__cvta_generic_to_shared(wbuf);
    const unsigned wend  = wbase + N_STAGE * BUF_FLT * 4;

    const int r    = lane & 3;     // row within warp-tile
    const int part = lane >> 2;    // 0..7: column eighth
    const bool me  = (part == 0);  // row-owner lanes 0..3

    // ---- per-lane staging geometry (constant): lane covers float4 indices
    //      k = lane, lane+32, lane+64 (+lane+96 if lane<4) ----
    const int k0 = lane, k1 = lane + 32, k2 = lane + 64, k3 = lane + 96;
    const int rr0 = k0 / 25, rr1 = k1 / 25, rr2 = k2 / 25, rr3 = k3 / 25;
    const unsigned d0 = (unsigned)(rr0 * (ROW_PAD * 4) + (k0 - rr0 * 25) * 16);
    const unsigned d1 = (unsigned)(rr1 * (ROW_PAD * 4) + (k1 - rr1 * 25) * 16);
    const unsigned d2 = (unsigned)(rr2 * (ROW_PAD * 4) + (k2 - rr2 * 25) * 16);
    const unsigned d3 = (unsigned)(rr3 * (ROW_PAD * 4) + (k3 - rr3 * 25) * 16);
    const bool do3 = (lane < 4);

    const char* src = reinterpret_cast<const char*>(
        reinterpret_cast<const float4*>(inp) + (size_t)gwarp * 100 + k0);
    const size_t srcstep = (size_t)NWARP * 1600;   // bytes per tile stride

    // rotating pointers
    unsigned dstb = wbase;                         // staging buffer base (bytes)
    const float* rdbase = wbuf + r * ROW_PAD;      // compute row base
    const float* rd     = rdbase;
    const int chunk = part * 3;

    float lsumf = 0.0f;
    int   n0_c0 = 0,    n0_c1 = 0;
    float sf_c0 = 0.0f, sf_c1 = 0.0f;

    // ---- prologue: stage tiles T and T+NWARP (2 groups) ----
    #pragma unroll
    for (int pre = 0; pre < 2; pre++) {
        if (gwarp + pre * NWARP < N_TILES) {
            CP16I(dstb + d0, src, 0);
            CP16I(dstb + d1, src, 512);
            CP16I(dstb + d2, src, 1024);
            if (do3) CP16I(dstb + d3, src, 1536);
            src += srcstep;
        }
        CP_COMMIT();
        dstb += BUF_FLT * 4;
    }

    for (int T = gwarp; T < N_TILES; T += NWARP) {
        // stage T + 2*NWARP into the free buffer; commit unconditionally
        if (T + 2 * NWARP < N_TILES) {
            CP16I(dstb + d0, src, 0);
            CP16I(dstb + d1, src, 512);
            CP16I(dstb + d2, src, 1024);
            if (do3) CP16I(dstb + d3, src, 1536);
            src += srcstep;
        }
        CP_COMMIT();
        dstb += BUF_FLT * 4;
        if (dstb == wend) dstb = wbase;

        CP_WAIT(2);            // tile T's group has drained
        __syncwarp();

        const float4* rowp = reinterpret_cast<const float4*>(rd);
        rd += BUF_FLT;
        if (rd == rdbase + N_STAGE * BUF_FLT) rd = rdbase;

        float sumE = 0.0f, sumE2 = 0.0f, e0 = 0.0f, e1 = 0.0f;
        #pragma unroll
        for (int k = 0; k < 3; k++) {
            float4 v = rowp[chunk + k];
            float x0 = ex2f(v.x * L2E), x1 = ex2f(v.y * L2E);
            float x2 = ex2f(v.z * L2E), x3 = ex2f(v.w * L2E);
            if (k == 0) { e0 = x0; e1 = x1; }     // part0's chunk0 = cols 0..3
            sumE += (x0 + x1) + (x2 + x3);
            sumE2 = fmaf(x0, x0, fmaf(x1, x1, fmaf(x2, x2, fmaf(x3, x3, sumE2))));
        }
        if (part == 7) {       // extra chunk 24
            float4 v = rowp[24];
            float x0 = ex2f(v.x * L2E), x1 = ex2f(v.y * L2E);
            float x2 = ex2f(v.z * L2E), x3 = ex2f(v.w * L2E);
            sumE += (x0 + x1) + (x2 + x3);
            sumE2 = fmaf(x0, x0, fmaf(x1, x1, fmaf(x2, x2, fmaf(x3, x3, sumE2))));
        }
        #pragma unroll
        for (int o = 4; o < 32; o <<= 1) {
            sumE  += __shfl_xor_sync(0xffffffffu, sumE, o);
            sumE2 += __shfl_xor_sync(0xffffffffu, sumE2, o);
        }

        if (me) {
            float iv = 1.0f / sumE;
            lsumf += sumE2 * iv * iv;        // sum_j p_j^2 = sumE2 / sumE^2
            float c0 = e0 * iv, c1 = e1 * iv;
            float x0 = c0 * 15.0f, x1 = c1 * 15.0f;
            // fast path: x<1 -> floor bin 0 AND ceil bin 0 (counts identical)
            if (x0 < 1.0f) { n0_c0++; sf_c0 += c0; }
            else {
                int bf = min(N_BINS - 1, (int)x0);
                int bc = min(N_BINS - 1, __float2int_ru(x0) - 1);
                atomicAdd(&g_cf[bf], 1); atomicAdd(&g_sf[bf], c0); atomicAdd(&g_cc[bc], 1);
            }
            if (x1 < 1.0f) { n0_c1++; sf_c1 += c1; }
            else {
                int bf = min(N_BINS - 1, (int)x1);
                int bc = min(N_BINS - 1, __float2int_ru(x1) - 1);
                atomicAdd(&g_cf[N_BINS + bf], 1);
                atomicAdd(&g_sf[N_BINS + bf], c1);
                atomicAdd(&g_cc[N_BINS + bc], 1);
            }
        }
    }

    // ---- fold fast-path counters: lanes 0..3 hold data, others zero ----
    n0_c0 += __shfl_xor_sync(0xffffffffu, n0_c0, 1);
    n0_c0 += __shfl_xor_sync(0xffffffffu, n0_c0, 2);
    n0_c1 += __shfl_xor_sync(0xffffffffu, n0_c1, 1);
    n0_c1 += __shfl_xor_sync(0xffffffffu, n0_c1, 2);
    sf_c0 += __shfl_xor_sync(0xffffffffu, sf_c0, 1);
    sf_c0 += __shfl_xor_sync(0xffffffffu, sf_c0, 2);
    sf_c1 += __shfl_xor_sync(0xffffffffu, sf_c1, 1);
    sf_c1 += __shfl_xor_sync(0xffffffffu, sf_c1, 2);

    double lsum = (double)lsumf;
    #pragma unroll
    for (int o = 16; o; o >>= 1) lsum += __shfl_xor_sync(0xffffffffu, lsum, o);

    if (lane == 0) {
        s_hi[wid][0] = n0_c0; s_hi[wid][1] = n0_c1;
        s_hf[wid][0] = sf_c0; s_hf[wid][1] = sf_c1;
        s_warp[wid]  = lsum;
    }
    __syncthreads();
    if (tid == 0) {
        double b = 0.0;
        #pragma unroll
        for (int i = 0; i < WARPS; i++) b += s_warp[i];
        atomicAdd(&g_sumsq, b);
    }
    if (tid < 2) {           // per-class bin0 flush (counts go to BOTH cf and cc)
        int n = 0; float sf = 0.0f;
        #pragma unroll
        for (int w = 0; w < WARPS; w++) { n += s_hi[w][tid]; sf += s_hf[w][tid]; }
        if (n) {
            atomicAdd(&g_cf[tid * N_BINS], n);
            atomicAdd(&g_cc[tid * N_BINS], n);
            atomicAdd(&g_sf[tid * N_BINS], sf);
        }
    }

    // ---- last-block finalize ----
    __threadfence();
    __syncthreads();
    if (tid == 0) s_last = (atomicAdd(&g_done, 1u) == gridDim.x - 1);
    __syncthreads();
    if (!s_last || tid >= 32) return;

    __threadfence();
    int t = tid;
    double part2 = 0.0;
    if (t < 2 * N_BINS) {
        int n = g_cc[t];
        if (n > 0) {
            float rm   = (t < N_BINS) ? 0.99f : 0.01f;
            float sums = seqsum_const_f32(rm, (unsigned)n);
            float acc  = sums / (float)n;
            double g = (double)acc;
            part2 = g * g * (double)g_cf[t] - 2.0 * g * (double)g_sf[t];
        }
    }
    #pragma unroll
    for (int o = 16; o; o >>= 1) part2 += __shfl_xor_sync(0xffffffffu, part2, o);
    if (t == 0) {
        double total = g_sumsq + part2;
        out[0] = (float)(total / (double)((long long)N_ROWS * N_COLS));
        g_sumsq = 0.0;
        g_done  = 0u;
    }
    if (t < 2 * N_BINS) { g_cc[t] = 0; g_cf[t] = 0; g_sf[t] = 0.0f; }
}

extern "C" void kernel_launch(void* const* d_in, const int* in_sizes, int n_in,
                              void* d_out, int out_size) {
    const float* inp = (const float*)d_in[0];
    // d_in[1] (target) is mathematically irrelevant: row means of
    // (onehot==0)/(onehot==1) are the constants 0.99 / 0.01 for every row.
    float* out = (float*)d_out;
    (void)in_sizes; (void)n_in; (void)out_size;

    const int smem = WARPS * N_STAGE * BUF_FLT * sizeof(float);   // 39,936 B
    KLECE_main<<<GRID, THREADS, smem>>>(inp, out);
}

// round 12
// speedup vs baseline: 1.0830x; 1.0830x over previous
#include <cuda_runtime.h>
#include <math.h>

#define N_ROWS   250000
#define N_COLS   100
#define N_BINS   15
#define THREADS  128
#define WARPS    4
#define W_ROWS   32                      // thread-per-row: one warp = 32 rows
#define TILE_F4  (W_ROWS * 25)           // 800 float4 per tile
#define TILE_FLT (W_ROWS * N_COLS)       // 3200 floats (12.8 KB)
#define N_TILES  ((N_ROWS + W_ROWS - 1) / W_ROWS)   // 7813 (last tile: 16 rows)
#define GRID     296                     // 148 SMs x 2 blocks (102.4KB smem each)
#define NWARP    (GRID * WARPS)          // 1184 warps

// Global accumulators. Zero at module load; the last block re-zeros them
// after finalizing so every graph replay starts clean.
__device__ double   g_sumsq;
__device__ int      g_cc[2 * N_BINS];
__device__ int      g_cf[2 * N_BINS];
__device__ float    g_sf[2 * N_BINS];
__device__ unsigned g_done;

__device__ __forceinline__ void cp16(unsigned dst, const void* src) {
    asm volatile("cp.async.cg.shared.global [%0], [%1], 16;" :: "r"(dst), "l"(src));
}
#define CP_COMMIT() asm volatile("cp.async.commit_group;" ::: "memory")
#define CP_WAIT(n)  asm volatile("cp.async.wait_group %0;" :: "n"(n) : "memory")

__device__ __forceinline__ float ex2f(float x) {
    float r; asm("ex2.approx.f32 %0, %1;" : "=f"(r) : "f"(x)); return r;
}
__device__ __forceinline__ float rcpf(float x) {
    float r; asm("rcp.approx.f32 %0, %1;" : "=f"(r) : "f"(x)); return r;
}
#define L2E 1.4426950408889634f

// Bit-exact model of n sequential fp32 RNE additions of the constant a
// (XLA scatter-add of identical addends is order-independent). All-integer:
// per-add increment is RNE(A * 2^(ea-e)) ulps; in-binade advance is u32
// mantissa arithmetic; one genuine fp32 add per binade crossing.
__device__ float seqsum_const_f32(float a, unsigned n) {
    unsigned ai = __float_as_uint(a);
    unsigned A  = (ai & 0x7FFFFFu) | 0x800000u;
    int      ea = (int)((ai >> 23) & 0xFF);
    float s = 0.0f;
    while (n > 0) {
        float s1 = s + a;
        if (s1 == s) break;
        s = s1; n--;
        if (n == 0) break;
        unsigned si   = __float_as_uint(s);
        int      e    = (int)((si >> 23) & 0xFF);
        unsigned mant = (si & 0x7FFFFFu) | 0x800000u;
        int sh = e - ea;
        unsigned step;
        if (sh <= 0)       step = A;
        else if (sh >= 25) step = 0;
        else {
            unsigned q = A >> sh, r = A & ((1u << sh) - 1u), half = 1u << (sh - 1);
            step = q + ((r > half || (r == half && (q & 1u))) ? 1u : 0u);
        }
        if (step != 0) {
            unsigned room = (0xFFFFFFu - mant) / step;
            unsigned m = room < n ? room : n;
            if (m > 0) {
                mant += m * step;
                s = __uint_as_float(((unsigned)e << 23) | (mant & 0x7FFFFFu));
                n -= m;
            }
        }
    }
    return s;
}

// Stage one tile: 800 float4 (or fewer for the partial last tile), 25 per lane.
__device__ __forceinline__ void stage(unsigned dst_lane, const float4* src_lane,
                                      int lane, bool full) {
    if (full) {
        #pragma unroll
        for (int i = 0; i < 25; i++)
            cp16(dst_lane + i * 512, src_lane + i * 32);
    } else {
        #pragma unroll
        for (int i = 0; i < 25; i++)
            if (lane + i * 32 < (N_ROWS % W_ROWS) * 25)   // 400 f4 in last tile
                cp16(dst_lane + i * 512, src_lane + i * 32);
    }
}

__global__ __launch_bounds__(THREADS) void KLECE_main(const float* __restrict__ inp,
                                                      float* __restrict__ out) {
    extern __shared__ float buf[];   // [WARPS][2][TILE_FLT]
    __shared__ int    s_hi[WARPS][2];
    __shared__ float  s_hf[WARPS][2];
    __shared__ double s_warp[WARPS];
    __shared__ bool   s_last;

    const int tid = threadIdx.x, lane = tid & 31, wid = tid >> 5;
    const int gwarp = blockIdx.x * WARPS + wid;

    float* wbuf = buf + wid * (2 * TILE_FLT);
    const unsigned dst_lane = (unsigned)__cvta_generic_to_shared(wbuf) + lane * 16;

    const float4* inp4 = reinterpret_cast<const float4*>(inp);
    const size_t  srcstep = (size_t)NWARP * TILE_F4;

    // per-thread row pointers in both buffers (thread-per-row; stride 100
    // floats is conflict-free for LDS.128: start banks 4*lane per 8-lane phase)
    const float4* rp0 = reinterpret_cast<const float4*>(wbuf) + lane * 25;
    const float4* rp1 = rp0 + TILE_FLT / 4;

    double lsum = 0.0;
    float  lsumf = 0.0f;
    int    n0_c0 = 0,    n0_c1 = 0;
    float  sf_c0 = 0.0f, sf_c1 = 0.0f;

    // ---- prologue: stage tile gwarp ----
    const float4* src = inp4 + (size_t)gwarp * TILE_F4 + lane;
    if (gwarp < N_TILES) stage(dst_lane, src, lane, gwarp != N_TILES - 1);
    src += srcstep;
    CP_COMMIT();

    for (int T = gwarp, par = 0; T < N_TILES; T += NWARP, par ^= 1) {
        int Tn = T + NWARP;
        if (Tn < N_TILES) {
            stage(dst_lane + (unsigned)((par ^ 1) * (TILE_FLT * 4)),
                  src, lane, Tn != N_TILES - 1);
            src += srcstep;
            CP_COMMIT();
            CP_WAIT(1);
        } else {
            CP_WAIT(0);
        }
        __syncwarp();

        const float4* rp = par ? rp1 : rp0;
        const bool valid = (T * W_ROWS + lane) < N_ROWS;

        float sE = 0.0f, sE2 = 0.0f, e0 = 0.0f, e1 = 0.0f;
        #pragma unroll
        for (int i = 0; i < 25; i++) {
            float4 v = rp[i];
            float x0 = ex2f(v.x * L2E), x1 = ex2f(v.y * L2E);
            float x2 = ex2f(v.z * L2E), x3 = ex2f(v.w * L2E);
            if (i == 0) { e0 = x0; e1 = x1; }
            sE  += (x0 + x1) + (x2 + x3);
            sE2 = fmaf(x0, x0, fmaf(x1, x1, fmaf(x2, x2, fmaf(x3, x3, sE2))));
        }

        float iv = rcpf(sE);
        if (valid) {
            lsumf += sE2 * iv * iv;          // sum_j p_j^2 = sE2 / sE^2
            float c0 = e0 * iv, c1 = e1 * iv;
            float x0 = c0 * 15.0f, x1 = c1 * 15.0f;
            // fast path: x<1 -> floor bin 0 AND ceil bin 0 (counts identical)
            if (x0 < 1.0f) { n0_c0++; sf_c0 += c0; }
            else {
                int bf = min(N_BINS - 1, (int)x0);
                int bc = min(N_BINS - 1, __float2int_ru(x0) - 1);
                atomicAdd(&g_cf[bf], 1); atomicAdd(&g_sf[bf], c0); atomicAdd(&g_cc[bc], 1);
            }
            if (x1 < 1.0f) { n0_c1++; sf_c1 += c1; }
            else {
                int bf = min(N_BINS - 1, (int)x1);
                int bc = min(N_BINS - 1, __float2int_ru(x1) - 1);
                atomicAdd(&g_cf[N_BINS + bf], 1);
                atomicAdd(&g_sf[N_BINS + bf], c1);
                atomicAdd(&g_cc[N_BINS + bc], 1);
            }
        }
    }

    // ---- warp reduction (once per kernel) ----
    lsum = (double)lsumf;
    #pragma unroll
    for (int o = 16; o; o >>= 1) {
        lsum  += __shfl_xor_sync(0xffffffffu, lsum, o);
        n0_c0 += __shfl_xor_sync(0xffffffffu, n0_c0, o);
        n0_c1 += __shfl_xor_sync(0xffffffffu, n0_c1, o);
        sf_c0 += __shfl_xor_sync(0xffffffffu, sf_c0, o);
        sf_c1 += __shfl_xor_sync(0xffffffffu, sf_c1, o);
    }
    if (lane == 0) {
        s_hi[wid][0] = n0_c0; s_hi[wid][1] = n0_c1;
        s_hf[wid][0] = sf_c0; s_hf[wid][1] = sf_c1;
        s_warp[wid]  = lsum;
    }
    __syncthreads();
    if (tid == 0) {
        double b = 0.0;
        #pragma unroll
        for (int i = 0; i < WARPS; i++) b += s_warp[i];
        atomicAdd(&g_sumsq, b);
    }
    if (tid < 2) {           // per-class bin0 flush (counts go to BOTH cf and cc)
        int n = 0; float sf = 0.0f;
        #pragma unroll
        for (int w = 0; w < WARPS; w++) { n += s_hi[w][tid]; sf += s_hf[w][tid]; }
        if (n) {
            atomicAdd(&g_cf[tid * N_BINS], n);
            atomicAdd(&g_cc[tid * N_BINS], n);
            atomicAdd(&g_sf[tid * N_BINS], sf);
        }
    }

    // ---- last-block finalize ----
    __threadfence();
    __syncthreads();
    if (tid == 0) s_last = (atomicAdd(&g_done, 1u) == gridDim.x - 1);
    __syncthreads();
    if (!s_last || tid >= 32) return;

    __threadfence();
    int t = tid;
    double part2 = 0.0;
    if (t < 2 * N_BINS) {
        int n = g_cc[t];
        if (n > 0) {
            float rm   = (t < N_BINS) ? 0.99f : 0.01f;
            float sums = seqsum_const_f32(rm, (unsigned)n);
            float acc  = sums / (float)n;
            double g = (double)acc;
            part2 = g * g * (double)g_cf[t] - 2.0 * g * (double)g_sf[t];
        }
    }
    #pragma unroll
    for (int o = 16; o; o >>= 1) part2 += __shfl_xor_sync(0xffffffffu, part2, o);
    if (t == 0) {
        double total = g_sumsq + part2;
        out[0] = (float)(total / (double)((long long)N_ROWS * N_COLS));
        g_sumsq = 0.0;
        g_done  = 0u;
    }
    if (t < 2 * N_BINS) { g_cc[t] = 0; g_cf[t] = 0; g_sf[t] = 0.0f; }
}

extern "C" void kernel_launch(void* const* d_in, const int* in_sizes, int n_in,
                              void* d_out, int out_size) {
    const float* inp = (const float*)d_in[0];
    // d_in[1] (target) is mathematically irrelevant: row means of
    // (onehot==0)/(onehot==1) are the constants 0.99 / 0.01 for every row.
    float* out = (float*)d_out;
    (void)in_sizes; (void)n_in; (void)out_size;

    const int smem = WARPS * 2 * TILE_FLT * sizeof(float);   // 102,400 B
    cudaFuncSetAttribute(KLECE_main, cudaFuncAttributeMaxDynamicSharedMemorySize, smem);
    KLECE_main<<<GRID, THREADS, smem>>>(inp, out);
}